// round 2
// baseline (speedup 1.0000x reference)
#include <cuda_runtime.h>

#define ND 32
#define NB 128
#define N0N1 16384
#define MAIN_CTAS 256
#define PPC (N0N1 / MAIN_CTAS)   /* 64 pairs per CTA */
#define PSTRIDE 68               /* floats per partial record (17 float4) */

// Scratch (static device globals; no allocation in kernel_launch).
// pack1[pair][g] = (nh_{2g}, P_{2g}, nh_{2g+1}, P_{2g+1})   nh = -0.5/Sigma, P = mut/Sigma
// pack2[pair][g] = ( K_{2g}, G_{2g},  K_{2g+1},  G_{2g+1})   G  = K*mut - v
__device__ float4 g_pack1[N0N1 * (ND/2)];
__device__ float4 g_pack2[N0N1 * (ND/2)];
__device__ float  g_c[N0N1];
__device__ float4 g_part4[MAIN_CTAS * NB * (PSTRIDE/4)];

// ---------------------------------------------------------------------------
// Kernel A: per-(i,j,n) geometry. One warp per (i,j) pair, lane = n.
// ---------------------------------------------------------------------------
__global__ void gmm_precompute(const float* __restrict__ t_in,
                               const float* __restrict__ Mu0,
                               const float* __restrict__ Mu1,
                               const float* __restrict__ S0,
                               const float* __restrict__ S1) {
    int gw = (blockIdx.x * blockDim.x + threadIdx.x) >> 5;   // pair index
    int n  = threadIdx.x & 31;                               // dim index
    if (gw >= N0N1) return;
    int i = gw >> 7, j = gw & 127;

    float t = t_in[0];
    float u = 1.0f - t;
    float s0 = S0[i*ND + n], s1 = S1[j*ND + n];
    float m0 = Mu0[i*ND + n], m1 = Mu1[j*ND + n];
    const float eps2 = 0.25f, eps4 = 0.0625f;

    float Ds    = sqrtf(4.0f*s0*s1 + eps4);
    float Cs    = 0.5f*(Ds - eps2);
    float Sigma = u*u*s0 + t*t*s1 + 2.0f*t*u*Cs + eps2*t*u;
    float St    = (t*s1 + u*Cs) - (u*s0 + t*Cs) - eps2*t;
    float rS    = 1.0f / Sigma;
    float K     = St * rS;
    float mut   = u*m0 + t*m1;
    float v     = m1 - m0;

    float nh = -0.5f * rS;
    float P  = rS * mut;
    float G  = K*mut - v;
    float clog = -0.5f*__logf(Sigma) + nh*mut*mut;  // per-dim constant part of logw

    float* p1 = (float*)g_pack1 + (size_t)gw*(2*ND);
    float* p2 = (float*)g_pack2 + (size_t)gw*(2*ND);
    int off = 4*(n>>1) + 2*(n&1);
    *(float2*)(p1 + off) = make_float2(nh, P);
    *(float2*)(p2 + off) = make_float2(K, G);

    #pragma unroll
    for (int s = 16; s; s >>= 1) clog += __shfl_xor_sync(0xffffffffu, clog, s);
    if (n == 0) g_c[gw] = clog;
}

// ---------------------------------------------------------------------------
// Kernel B: main accumulation. CTA = 64 pairs staged in smem; thread = batch b.
// ---------------------------------------------------------------------------
__global__ void __launch_bounds__(NB) gmm_main(const float* __restrict__ X,
                                               const float* __restrict__ Lam) {
    __shared__ float4 s1[PPC*16];
    __shared__ float4 s2[PPC*16];
    __shared__ float  sc[PPC];
    __shared__ float  slam[PPC];

    int b = threadIdx.x;
    int pair0 = blockIdx.x * PPC;

    #pragma unroll 1
    for (int k = threadIdx.x; k < PPC*16; k += NB) {
        s1[k] = g_pack1[pair0*16 + k];
        s2[k] = g_pack2[pair0*16 + k];
    }
    if (threadIdx.x < PPC) {
        sc[threadIdx.x]   = g_c[pair0 + threadIdx.x];
        slam[threadIdx.x] = Lam[pair0 + threadIdx.x];
    }

    float x[ND], xs[ND];
    const float4* Xv = (const float4*)(X + b*ND);
    #pragma unroll
    for (int g = 0; g < ND/4; g++) {
        float4 xv = Xv[g];
        x[4*g+0] = xv.x; x[4*g+1] = xv.y; x[4*g+2] = xv.z; x[4*g+3] = xv.w;
    }
    #pragma unroll
    for (int n = 0; n < ND; n++) xs[n] = x[n]*x[n];

    float aK[ND], aG[ND];
    #pragma unroll
    for (int n = 0; n < ND; n++) { aK[n] = 0.f; aG[n] = 0.f; }
    float den = 0.f;

    __syncthreads();

    #pragma unroll 1
    for (int p = 0; p < PPC; p++) {
        const float4* q1 = s1 + p*16;
        float lw[4] = { sc[p], 0.f, 0.f, 0.f };   // 4 chains to break FMA latency
        #pragma unroll
        for (int g = 0; g < 16; g++) {
            float4 a = q1[g];
            lw[g&3] = fmaf(a.x, xs[2*g],   lw[g&3]);
            lw[g&3] = fmaf(a.y, x[2*g],    lw[g&3]);
            lw[g&3] = fmaf(a.z, xs[2*g+1], lw[g&3]);
            lw[g&3] = fmaf(a.w, x[2*g+1],  lw[g&3]);
        }
        float lws = (lw[0]+lw[1]) + (lw[2]+lw[3]);
        float w = __expf(fminf(fmaxf(lws, -50.f), 50.f)) * slam[p];
        den += w;

        const float4* q2 = s2 + p*16;
        #pragma unroll
        for (int g = 0; g < 16; g++) {
            float4 kg = q2[g];
            aK[2*g]   = fmaf(w, kg.x, aK[2*g]);
            aG[2*g]   = fmaf(w, kg.y, aG[2*g]);
            aK[2*g+1] = fmaf(w, kg.z, aK[2*g+1]);
            aG[2*g+1] = fmaf(w, kg.w, aG[2*g+1]);
        }
    }

    float* pp = (float*)g_part4 + (size_t)(blockIdx.x*NB + b)*PSTRIDE;
    float4* pv = (float4*)pp;
    #pragma unroll
    for (int g = 0; g < 8; g++)
        pv[g]   = make_float4(aK[4*g], aK[4*g+1], aK[4*g+2], aK[4*g+3]);
    #pragma unroll
    for (int g = 0; g < 8; g++)
        pv[8+g] = make_float4(aG[4*g], aG[4*g+1], aG[4*g+2], aG[4*g+3]);
    pp[64] = den;
}

// ---------------------------------------------------------------------------
// Kernel C: reduce partials across 256 CTAs and finalize num/den.
// ---------------------------------------------------------------------------
__global__ void __launch_bounds__(128) gmm_reduce(const float* __restrict__ X,
                                                  float* __restrict__ out) {
    __shared__ float rK[128], rG[128], rD[128];
    int b = blockIdx.x;
    int tid = threadIdx.x;
    int n = tid & 31, q = tid >> 5;

    float sK = 0.f, sG = 0.f, dn = 0.f;
    const float* base = (const float*)g_part4 + (size_t)b*PSTRIDE;
    #pragma unroll 4
    for (int c = q*(MAIN_CTAS/4); c < (q+1)*(MAIN_CTAS/4); c++) {
        const float* pp = base + (size_t)c*(NB*PSTRIDE);
        sK += pp[n];
        sG += pp[32+n];
        dn += pp[64];
    }
    rK[tid] = sK; rG[tid] = sG; rD[tid] = dn;
    __syncthreads();
    if (q == 0) {
        sK = (rK[n]+rK[n+32]) + (rK[n+64]+rK[n+96]);
        sG = (rG[n]+rG[n+32]) + (rG[n+64]+rG[n+96]);
        dn = (rD[n]+rD[n+32]) + (rD[n+64]+rD[n+96]);
        out[b*ND + n] = (X[b*ND + n]*sK - sG) / dn;
    }
}

// ---------------------------------------------------------------------------
extern "C" void kernel_launch(void* const* d_in, const int* in_sizes, int n_in,
                              void* d_out, int out_size) {
    const float* X   = (const float*)d_in[0];
    const float* t   = (const float*)d_in[1];
    const float* Mu0 = (const float*)d_in[2];
    const float* Mu1 = (const float*)d_in[3];
    const float* S0  = (const float*)d_in[4];
    const float* S1  = (const float*)d_in[5];
    const float* Lam = (const float*)d_in[6];
    float* out = (float*)d_out;

    gmm_precompute<<<N0N1/8, 256>>>(t, Mu0, Mu1, S0, S1);
    gmm_main<<<MAIN_CTAS, NB>>>(X, Lam);
    gmm_reduce<<<NB, 128>>>(X, out);
}

// round 3
// speedup vs baseline: 1.1088x; 1.1088x over previous
#include <cuda_runtime.h>

#define ND 32
#define NB 128
#define N0N1 16384
#define MAIN_CTAS 512
#define PPC (N0N1 / MAIN_CTAS)   /* 32 pairs per CTA */
#define PSTRIDE 68               /* floats per partial record (17 float4) */

__device__ float4 g_part4[MAIN_CTAS * NB * (PSTRIDE/4)];

typedef unsigned long long u64;

// ---- packed f32x2 helpers (sm_100+) --------------------------------------
__device__ __forceinline__ u64 pk2(float lo, float hi) {
    u64 r; asm("mov.b64 %0,{%1,%2};" : "=l"(r) : "f"(lo), "f"(hi)); return r;
}
__device__ __forceinline__ u64 fma2(u64 a, u64 b, u64 c) {
    u64 d; asm("fma.rn.f32x2 %0,%1,%2,%3;" : "=l"(d) : "l"(a), "l"(b), "l"(c)); return d;
}
__device__ __forceinline__ u64 add2(u64 a, u64 b) {
    u64 d; asm("add.rn.f32x2 %0,%1,%2;" : "=l"(d) : "l"(a), "l"(b)); return d;
}
__device__ __forceinline__ float2 upk(u64 a) {
    float lo, hi; asm("mov.b64 {%0,%1},%2;" : "=f"(lo), "=f"(hi) : "l"(a));
    return make_float2(lo, hi);
}

// ---- per-dim geometry ----------------------------------------------------
struct Geo { float nh, P, K, G, cl; };
__device__ __forceinline__ Geo geo(float s0, float s1, float m0, float m1,
                                   float t, float u) {
    const float eps2 = 0.25f, eps4 = 0.0625f;
    float Ds    = sqrtf(fmaf(4.0f*s0, s1, eps4));
    float Cs    = 0.5f*(Ds - eps2);
    float Sigma = u*u*s0 + t*t*s1 + 2.0f*t*u*Cs + eps2*t*u;
    float St    = (t*s1 + u*Cs) - (u*s0 + t*Cs) - eps2*t;
    float rS    = __fdividef(1.0f, Sigma);
    float mut   = u*m0 + t*m1;
    Geo g;
    g.K  = St * rS;
    g.nh = -0.5f * rS;
    g.P  = rS * mut;
    g.G  = g.K*mut - (m1 - m0);
    g.cl = fmaf(g.nh, mut*mut, -0.5f*__logf(Sigma));
    return g;
}

// ---------------------------------------------------------------------------
// Fused kernel: prologue computes this CTA's 32 pairs' packs into smem,
// main loop: thread = (batch b, half h), 16 dims each, f32x2 packed math.
// smem layout (per pair): 16 ulonglong2, index = (gg&7)*2 + (gg>>3)
//   s1 entry = (nh01, P01), s2 entry = (K01, G01) for global dim-pair gg.
// ---------------------------------------------------------------------------
__global__ void __launch_bounds__(256) gmm_main(
    const float* __restrict__ X,   const float* __restrict__ t_in,
    const float* __restrict__ Mu0, const float* __restrict__ Mu1,
    const float* __restrict__ S0,  const float* __restrict__ S1,
    const float* __restrict__ Lam)
{
    __shared__ ulonglong2 s1[PPC*16];
    __shared__ ulonglong2 s2[PPC*16];
    __shared__ float sc[PPC];
    __shared__ float slam[PPC];

    int tid = threadIdx.x;

    // ---------------- prologue: 8 threads per pair, 4 dims each ----------
    {
        int pl = tid >> 3, q = tid & 7;               // pair-local, dim quad
        int pair = blockIdx.x * PPC + pl;
        int i = pair >> 7, j = pair & 127;
        float t = t_in[0], u = 1.0f - t;

        float4 s0v = *(const float4*)(S0  + i*ND + q*4);
        float4 s1v = *(const float4*)(S1  + j*ND + q*4);
        float4 m0v = *(const float4*)(Mu0 + i*ND + q*4);
        float4 m1v = *(const float4*)(Mu1 + j*ND + q*4);

        Geo g0 = geo(s0v.x, s1v.x, m0v.x, m1v.x, t, u);
        Geo g1 = geo(s0v.y, s1v.y, m0v.y, m1v.y, t, u);
        Geo g2 = geo(s0v.z, s1v.z, m0v.z, m1v.z, t, u);
        Geo g3 = geo(s0v.w, s1v.w, m0v.w, m1v.w, t, u);

        int ggA = 2*q, ggB = 2*q + 1;                 // global dim-pairs
        int iA = pl*16 + (ggA & 7)*2 + (ggA >> 3);
        int iB = pl*16 + (ggB & 7)*2 + (ggB >> 3);
        s1[iA] = make_ulonglong2(pk2(g0.nh, g1.nh), pk2(g0.P, g1.P));
        s2[iA] = make_ulonglong2(pk2(g0.K,  g1.K ), pk2(g0.G, g1.G));
        s1[iB] = make_ulonglong2(pk2(g2.nh, g3.nh), pk2(g2.P, g3.P));
        s2[iB] = make_ulonglong2(pk2(g2.K,  g3.K ), pk2(g2.G, g3.G));

        float cl = ((g0.cl + g1.cl) + (g2.cl + g3.cl));
        cl += __shfl_xor_sync(0xffffffffu, cl, 1);
        cl += __shfl_xor_sync(0xffffffffu, cl, 2);
        cl += __shfl_xor_sync(0xffffffffu, cl, 4);
        if (q == 0) { sc[pl] = cl; slam[pl] = Lam[pair]; }
    }

    // ---------------- main loop: thread = (b, half) -----------------------
    int b = tid >> 1, h = tid & 1;

    u64 x2[8];
    {
        const ulonglong2* Xv = (const ulonglong2*)(X + b*ND + h*16);
        #pragma unroll
        for (int g = 0; g < 4; g++) {
            ulonglong2 xx = Xv[g];
            x2[2*g] = xx.x; x2[2*g+1] = xx.y;
        }
    }
    u64 aK2[8], aG2[8];
    #pragma unroll
    for (int g = 0; g < 8; g++) { aK2[g] = 0ull; aG2[g] = 0ull; }
    float den = 0.f;

    __syncthreads();

    #pragma unroll 1
    for (int p = 0; p < PPC; p++) {
        const ulonglong2* q1 = s1 + p*16 + h;
        u64 c0 = 0ull, c1 = 0ull;
        #pragma unroll
        for (int g = 0; g < 8; g++) {
            ulonglong2 a = q1[g*2];
            u64 tmp = fma2(a.x, x2[g], a.y);          // nh*x + P
            if (g & 1) c1 = fma2(tmp, x2[g], c1);     // (nh*x + P)*x
            else       c0 = fma2(tmp, x2[g], c0);
        }
        float2 cf = upk(add2(c0, c1));
        float lwh = cf.x + cf.y;
        float lws = lwh + __shfl_xor_sync(0xffffffffu, lwh, 1) + sc[p];
        float w = __expf(fminf(fmaxf(lws, -50.f), 50.f)) * slam[p];
        den += w;
        u64 w2 = pk2(w, w);
        const ulonglong2* q2 = s2 + p*16 + h;
        #pragma unroll
        for (int g = 0; g < 8; g++) {
            ulonglong2 kg = q2[g*2];
            aK2[g] = fma2(w2, kg.x, aK2[g]);
            aG2[g] = fma2(w2, kg.y, aG2[g]);
        }
    }

    float* pp = (float*)g_part4 + (size_t)(blockIdx.x*NB + b)*PSTRIDE;
    ulonglong2* pv = (ulonglong2*)pp;
    #pragma unroll
    for (int g = 0; g < 4; g++)
        pv[h*4 + g] = make_ulonglong2(aK2[2*g], aK2[2*g+1]);
    #pragma unroll
    for (int g = 0; g < 4; g++)
        pv[8 + h*4 + g] = make_ulonglong2(aG2[2*g], aG2[2*g+1]);
    if (h == 0) pp[64] = den;
}

// ---------------------------------------------------------------------------
// Reduce: block = b, 256 threads (8 quads of 32 lanes), 64 chunks per quad.
// ---------------------------------------------------------------------------
__global__ void __launch_bounds__(256) gmm_reduce(const float* __restrict__ X,
                                                  float* __restrict__ out) {
    __shared__ float rK[256], rG[256], rD[256];
    int b = blockIdx.x;
    int tid = threadIdx.x;
    int n = tid & 31, q = tid >> 5;

    float sK = 0.f, sG = 0.f, dn = 0.f;
    const float* base = (const float*)g_part4 + (size_t)b*PSTRIDE;
    #pragma unroll 4
    for (int c = q*(MAIN_CTAS/8); c < (q+1)*(MAIN_CTAS/8); c++) {
        const float* pp = base + (size_t)c*(NB*PSTRIDE);
        sK += pp[n];
        sG += pp[32+n];
        dn += pp[64];
    }
    rK[tid] = sK; rG[tid] = sG; rD[tid] = dn;
    __syncthreads();
    if (q == 0) {
        #pragma unroll
        for (int r = 1; r < 8; r++) {
            sK += rK[n + 32*r]; sG += rG[n + 32*r]; dn += rD[n + 32*r];
        }
        out[b*ND + n] = (X[b*ND + n]*sK - sG) / dn;
    }
}

// ---------------------------------------------------------------------------
extern "C" void kernel_launch(void* const* d_in, const int* in_sizes, int n_in,
                              void* d_out, int out_size) {
    const float* X   = (const float*)d_in[0];
    const float* t   = (const float*)d_in[1];
    const float* Mu0 = (const float*)d_in[2];
    const float* Mu1 = (const float*)d_in[3];
    const float* S0  = (const float*)d_in[4];
    const float* S1  = (const float*)d_in[5];
    const float* Lam = (const float*)d_in[6];
    float* out = (float*)d_out;

    gmm_main<<<MAIN_CTAS, 256>>>(X, t, Mu0, Mu1, S0, S1, Lam);
    gmm_reduce<<<NB, 256>>>(X, out);
}